// round 12
// baseline (speedup 1.0000x reference)
#include <cuda_runtime.h>
#include <cuda_bf16.h>
#include <cstddef>

#define BATCH   8
#define SEQ     2048
#define DMODEL  1024
#define DINT    64
#define DOUT    64
#define BT      (BATCH * SEQ)

// Static device scratch (no allocations), 16B-aligned for vector access.
__device__ __align__(16) float g_qkv[3][(size_t)BT * DINT];   // projected K,Q,V
__device__ __align__(16) float g_part[512][64][64];           // split-K partial ctx
__device__ __align__(16) float g_ml[512][2][64];              // split-K m (0), l (1)

// ---------------------------------------------------------------------------
// tf32 mma.sync m16n8k8 (raw fp32 bits as tf32 operands — HW reads top 19 bits)
// A frag: a0:(g,t) a1:(g+8,t) a2:(g,t+4) a3:(g+8,t+4)   [g=lane>>2, t=lane&3]
// B frag: b0:(k=t,n=g) b1:(k=t+4,n=g)
// C frag: c0:(g,2t) c1:(g,2t+1) c2:(g+8,2t) c3:(g+8,2t+1)
// ---------------------------------------------------------------------------
__device__ __forceinline__ void mma_tf32(float* c, const unsigned* a, const unsigned* b) {
    asm volatile(
        "mma.sync.aligned.m16n8k8.row.col.f32.tf32.tf32.f32 "
        "{%0,%1,%2,%3}, {%4,%5,%6,%7}, {%8,%9}, {%0,%1,%2,%3};\n"
        : "+f"(c[0]), "+f"(c[1]), "+f"(c[2]), "+f"(c[3])
        : "r"(a[0]), "r"(a[1]), "r"(a[2]), "r"(a[3]), "r"(b[0]), "r"(b[1]));
}

// cp.async helpers (16B copies, L1-cached)
__device__ __forceinline__ void cp16(unsigned* smem_dst, const void* gptr) {
    unsigned saddr = (unsigned)__cvta_generic_to_shared(smem_dst);
    asm volatile("cp.async.ca.shared.global [%0], [%1], 16;\n"
                 :: "r"(saddr), "l"(gptr));
}
#define CP_COMMIT() asm volatile("cp.async.commit_group;\n" ::: "memory")
#define CP_WAIT1()  asm volatile("cp.async.wait_group 1;\n" ::: "memory")
#define CP_WAIT0()  asm volatile("cp.async.wait_group 0;\n" ::: "memory")

// ---------------------------------------------------------------------------
// Kernel 1: fused QKV projection (tf32), 2-stage cp.async pipeline.
// Block: 64 rows x 96 cols, 128 threads = 4 warps (2x2), warp tile 32x48.
// Grid = 256 row-tiles x 2 col-halves = 512 blocks.
// ---------------------------------------------------------------------------
#define PKC 32
#define SXS 36        // xs stride (words): A-load banks g*4+t conflict-free
#define SWS 104       // ws stride (words): B-load banks t*8+g conflict-free
#define XS_W (64 * SXS)
#define WS_W (PKC * SWS)
#define NKIT (DMODEL / PKC)   // 32

__global__ void __launch_bounds__(128)
proj_kernel(const float* __restrict__ X,
            const float* __restrict__ Wk, const float* __restrict__ bk,
            const float* __restrict__ Wq, const float* __restrict__ bq,
            const float* __restrict__ Wv, const float* __restrict__ bv)
{
    __shared__ unsigned xs[2][XS_W];
    __shared__ unsigned ws[2][WS_W];

    const int tid  = threadIdx.x;
    const int wid  = tid >> 5, lane = tid & 31;
    const int g    = lane >> 2, t = lane & 3;
    const int wm   = wid >> 1, wn = wid & 1;
    const int row0 = (blockIdx.x >> 1) * 64;
    const int cg0  = (blockIdx.x & 1) * 96;
    const int wrow = wm * 32;
    const int wcol = wn * 48;

    // per-thread fixed staging assignments
    // X: 512 uint4 -> 4 per thread ; W: 768 uint4 -> 6 per thread
    #define PROJ_STAGE(st, kc)                                                  \
    {                                                                           \
        _Pragma("unroll")                                                       \
        for (int i = tid; i < 64 * 8; i += 128) {                               \
            int r = i >> 3, c4 = (i & 7) * 4;                                   \
            cp16(&xs[st][r * SXS + c4],                                         \
                 &X[(size_t)(row0 + r) * DMODEL + (kc) + c4]);                  \
        }                                                                       \
        _Pragma("unroll")                                                       \
        for (int i = tid; i < PKC * 24; i += 128) {                             \
            int r = i / 24, f = i - r * 24;                                     \
            int col = cg0 + f * 4;                                              \
            const float* wsrc = (col < 64) ? Wk : ((col < 128) ? Wq : Wv);      \
            cp16(&ws[st][r * SWS + f * 4],                                      \
                 &wsrc[(size_t)((kc) + r) * 64 + (col & 63)]);                  \
        }                                                                       \
    }

    float acc[2][6][4];
    #pragma unroll
    for (int mi = 0; mi < 2; mi++)
        #pragma unroll
        for (int ni = 0; ni < 6; ni++)
            #pragma unroll
            for (int e = 0; e < 4; e++) acc[mi][ni][e] = 0.f;

    PROJ_STAGE(0, 0);
    CP_COMMIT();

    for (int it = 0; it < NKIT; it++) {
        const int st = it & 1;
        if (it + 1 < NKIT) {
            PROJ_STAGE(st ^ 1, (it + 1) * PKC);
            CP_COMMIT();
            CP_WAIT1();
        } else {
            CP_WAIT0();
        }
        __syncthreads();

        #pragma unroll
        for (int ks = 0; ks < PKC; ks += 8) {
            unsigned a[2][4];
            #pragma unroll
            for (int mi = 0; mi < 2; mi++) {
                int r = wrow + mi * 16;
                a[mi][0] = xs[st][(r + g)     * SXS + ks + t];
                a[mi][1] = xs[st][(r + g + 8) * SXS + ks + t];
                a[mi][2] = xs[st][(r + g)     * SXS + ks + t + 4];
                a[mi][3] = xs[st][(r + g + 8) * SXS + ks + t + 4];
            }
            #pragma unroll
            for (int ni = 0; ni < 6; ni++) {
                unsigned b[2];
                int c0 = wcol + ni * 8;
                b[0] = ws[st][(ks + t)     * SWS + c0 + g];
                b[1] = ws[st][(ks + t + 4) * SWS + c0 + g];
                mma_tf32(acc[0][ni], a[0], b);
                mma_tf32(acc[1][ni], a[1], b);
            }
        }
        __syncthreads();
    }

    // epilogue: bias + scatter to g_qkv (p: 0=K, 1=Q, 2=V)
    #pragma unroll
    for (int ni = 0; ni < 6; ni++) {
        int gc = cg0 + wcol + ni * 8 + 2 * t;       // even
        int p  = gc >> 6, cc = gc & 63;
        const float* bs = (p == 0) ? bk : ((p == 1) ? bq : bv);
        float bi0 = bs[cc], bi1 = bs[cc + 1];
        #pragma unroll
        for (int mi = 0; mi < 2; mi++) {
            int r = row0 + wrow + mi * 16 + g;
            *(float2*)&g_qkv[p][(size_t)r * DINT + cc] =
                make_float2(acc[mi][ni][0] + bi0, acc[mi][ni][1] + bi1);
            *(float2*)&g_qkv[p][(size_t)(r + 8) * DINT + cc] =
                make_float2(acc[mi][ni][2] + bi0, acc[mi][ni][3] + bi1);
        }
    }
    #undef PROJ_STAGE
}

// ---------------------------------------------------------------------------
// Kernel 2: causal flash attention, split-K (2 halves), 2-stage cp.async K/V.
// BM=64, BN=64, 128 threads = 4 warps x 16 rows, 2 CTAs/SM (87KB smem).
// Grid 512 = 32 q-tiles x 2 halves x 8 batches, largest q-tiles first.
// ---------------------------------------------------------------------------
#define KSS 68
#define VSS 72
#define PSS 68
#define KS_N (64 * KSS)
#define VS_N (64 * VSS)
#define PS_N (64 * PSS)
#define ATTN_SMEM_BYTES ((2 * KS_N + 2 * VS_N + PS_N) * (int)sizeof(unsigned))

__global__ void __launch_bounds__(128, 2)
attn_kernel()
{
    extern __shared__ unsigned sm[];
    unsigned* ksb[2] = { sm, sm + KS_N };
    unsigned* vsb[2] = { sm + 2 * KS_N, sm + 2 * KS_N + VS_N };
    unsigned* ps     = sm + 2 * KS_N + 2 * VS_N;   // Q staging, then P

    const int tid = threadIdx.x, wid = tid >> 5, lane = tid & 31;
    const int g = lane >> 2, t = lane & 3;
    const int bid  = blockIdx.x;
    const int qi   = 31 - (bid >> 4);        // largest first
    const int rem  = bid & 15;
    const int half = rem >> 3;
    const int b    = rem & 7;
    const int q0   = qi * 64;
    const int wrow = wid * 16;

    const int n  = qi + 1;
    const int h  = (n + 1) >> 1;
    const int j0 = half ? h : 0;
    const int j1 = half ? n : h;

    const float* Kp = g_qkv[0] + (size_t)b * SEQ * DINT;
    const float* Qp = g_qkv[1] + (size_t)b * SEQ * DINT;
    const float* Vp = g_qkv[2] + (size_t)b * SEQ * DINT;

    #define KV_STAGE(st, k0)                                                    \
    {                                                                           \
        _Pragma("unroll")                                                       \
        for (int i = tid; i < 64 * 16; i += 128) {                              \
            int r = i >> 4, c4 = (i & 15) * 4;                                  \
            cp16(&ksb[st][r * KSS + c4], &Kp[(size_t)((k0) + r) * DINT + c4]);  \
            cp16(&vsb[st][r * VSS + c4], &Vp[(size_t)((k0) + r) * DINT + c4]);  \
        }                                                                       \
    }

    // prologue: start K/V stage 0 before Q staging (overlap)
    if (j0 < j1) {
        KV_STAGE(0, j0 * 64);
        CP_COMMIT();
    }

    // stage Q (pre-scaled by 1/8 — exponent-only, exact) as raw bits
    #pragma unroll
    for (int i = tid; i < 64 * 16; i += 128) {
        int r = i >> 4, c4 = (i & 15) * 4;
        float4 q = *(const float4*)&Qp[(size_t)(q0 + r) * DINT + c4];
        ps[r * PSS + c4 + 0] = __float_as_uint(q.x * 0.125f);
        ps[r * PSS + c4 + 1] = __float_as_uint(q.y * 0.125f);
        ps[r * PSS + c4 + 2] = __float_as_uint(q.z * 0.125f);
        ps[r * PSS + c4 + 3] = __float_as_uint(q.w * 0.125f);
    }
    __syncthreads();

    unsigned qf[8][4];
    #pragma unroll
    for (int kf = 0; kf < 8; kf++) {
        qf[kf][0] = ps[(wrow + g)     * PSS + kf * 8 + t];
        qf[kf][1] = ps[(wrow + g + 8) * PSS + kf * 8 + t];
        qf[kf][2] = ps[(wrow + g)     * PSS + kf * 8 + t + 4];
        qf[kf][3] = ps[(wrow + g + 8) * PSS + kf * 8 + t + 4];
    }
    __syncthreads();

    float ctx[8][4];
    #pragma unroll
    for (int nf = 0; nf < 8; nf++)
        #pragma unroll
        for (int e = 0; e < 4; e++) ctx[nf][e] = 0.f;
    float m0 = -1e30f, m1 = -1e30f, l0 = 0.f, l1 = 0.f;

    for (int j = j0; j < j1; j++) {
        const int k0 = j * 64;
        const int st = (j - j0) & 1;

        // prefetch next K/V into the other buffer (prev compute done: end barrier)
        if (j + 1 < j1) {
            KV_STAGE(st ^ 1, (j + 1) * 64);
            CP_COMMIT();
            CP_WAIT1();
        } else {
            CP_WAIT0();
        }
        __syncthreads();

        const unsigned* ks = ksb[st];
        const unsigned* vs = vsb[st];

        // ---- S = Q K^T ----
        float s[8][4];
        #pragma unroll
        for (int nf = 0; nf < 8; nf++)
            #pragma unroll
            for (int e = 0; e < 4; e++) s[nf][e] = 0.f;

        #pragma unroll
        for (int kf = 0; kf < 8; kf++) {
            #pragma unroll
            for (int nf = 0; nf < 8; nf++) {
                unsigned bb[2];
                bb[0] = ks[(nf * 8 + g) * KSS + kf * 8 + t];
                bb[1] = ks[(nf * 8 + g) * KSS + kf * 8 + t + 4];
                mma_tf32(s[nf], qf[kf], bb);
            }
        }

        // causal mask (diagonal tile only)
        if (k0 + 63 > q0 + wrow) {
            const int r0r = q0 + wrow + g, r1r = r0r + 8;
            #pragma unroll
            for (int nf = 0; nf < 8; nf++) {
                int key = k0 + nf * 8 + 2 * t;
                if (key     > r0r) s[nf][0] = -1e30f;
                if (key + 1 > r0r) s[nf][1] = -1e30f;
                if (key     > r1r) s[nf][2] = -1e30f;
                if (key + 1 > r1r) s[nf][3] = -1e30f;
            }
        }

        // ---- online softmax ----
        float mx0 = -1e30f, mx1 = -1e30f;
        #pragma unroll
        for (int nf = 0; nf < 8; nf++) {
            mx0 = fmaxf(mx0, fmaxf(s[nf][0], s[nf][1]));
            mx1 = fmaxf(mx1, fmaxf(s[nf][2], s[nf][3]));
        }
        mx0 = fmaxf(mx0, __shfl_xor_sync(0xffffffffu, mx0, 1));
        mx0 = fmaxf(mx0, __shfl_xor_sync(0xffffffffu, mx0, 2));
        mx1 = fmaxf(mx1, __shfl_xor_sync(0xffffffffu, mx1, 1));
        mx1 = fmaxf(mx1, __shfl_xor_sync(0xffffffffu, mx1, 2));

        const float nm0 = fmaxf(m0, mx0), nm1 = fmaxf(m1, mx1);
        const float f0 = __expf(m0 - nm0), f1 = __expf(m1 - nm1);

        float rs0 = 0.f, rs1 = 0.f;
        #pragma unroll
        for (int nf = 0; nf < 8; nf++) {
            float p00 = __expf(s[nf][0] - nm0);
            float p01 = __expf(s[nf][1] - nm0);
            float p10 = __expf(s[nf][2] - nm1);
            float p11 = __expf(s[nf][3] - nm1);
            rs0 += p00 + p01;
            rs1 += p10 + p11;
            ps[(wrow + g)     * PSS + nf * 8 + 2 * t]     = __float_as_uint(p00);
            ps[(wrow + g)     * PSS + nf * 8 + 2 * t + 1] = __float_as_uint(p01);
            ps[(wrow + g + 8) * PSS + nf * 8 + 2 * t]     = __float_as_uint(p10);
            ps[(wrow + g + 8) * PSS + nf * 8 + 2 * t + 1] = __float_as_uint(p11);
        }
        rs0 += __shfl_xor_sync(0xffffffffu, rs0, 1);
        rs0 += __shfl_xor_sync(0xffffffffu, rs0, 2);
        rs1 += __shfl_xor_sync(0xffffffffu, rs1, 1);
        rs1 += __shfl_xor_sync(0xffffffffu, rs1, 2);

        l0 = l0 * f0 + rs0;  m0 = nm0;
        l1 = l1 * f1 + rs1;  m1 = nm1;
        #pragma unroll
        for (int nf = 0; nf < 8; nf++) {
            ctx[nf][0] *= f0; ctx[nf][1] *= f0;
            ctx[nf][2] *= f1; ctx[nf][3] *= f1;
        }
        __syncwarp();   // own-warp P stores -> own-warp A-frag loads

        // ---- ctx += P V ----
        #pragma unroll
        for (int kf = 0; kf < 8; kf++) {
            unsigned pa[4];
            pa[0] = ps[(wrow + g)     * PSS + kf * 8 + t];
            pa[1] = ps[(wrow + g + 8) * PSS + kf * 8 + t];
            pa[2] = ps[(wrow + g)     * PSS + kf * 8 + t + 4];
            pa[3] = ps[(wrow + g + 8) * PSS + kf * 8 + t + 4];
            #pragma unroll
            for (int nf = 0; nf < 8; nf++) {
                unsigned bb[2];
                bb[0] = vs[(kf * 8 + t)     * VSS + nf * 8 + g];
                bb[1] = vs[(kf * 8 + t + 4) * VSS + nf * 8 + g];
                mma_tf32(ctx[nf], pa, bb);
            }
        }
        __syncthreads();   // all warps done with ks/vs/P before next prefetch
    }

    // ---- write partial state to scratch ----
    if (t == 0) {
        int r = wrow + g;
        g_ml[bid][0][r]     = m0;  g_ml[bid][1][r]     = l0;
        g_ml[bid][0][r + 8] = m1;  g_ml[bid][1][r + 8] = l1;
    }
    #pragma unroll
    for (int nf = 0; nf < 8; nf++) {
        *(float2*)&g_part[bid][wrow + g][nf * 8 + 2 * t] =
            make_float2(ctx[nf][0], ctx[nf][1]);
        *(float2*)&g_part[bid][wrow + g + 8][nf * 8 + 2 * t] =
            make_float2(ctx[nf][2], ctx[nf][3]);
    }
    #undef KV_STAGE
}

// ---------------------------------------------------------------------------
// Kernel 3: merge split-K halves + output projection + bias (fp32 FFMA).
// Grid 256 = 32 q-tiles x 8 batches, 256 threads (16x16, 4x4 tiles).
// ---------------------------------------------------------------------------
#define W0S 68   // stride mult of 4 words: float4 staging stays 16B-aligned

__global__ void __launch_bounds__(256)
combine_kernel(float* __restrict__ out,
               const float* __restrict__ W0, const float* __restrict__ b0)
{
    __shared__ float cs[64][65];       // scalar access only
    __shared__ float w0s[64][W0S];     // float4-staged

    const int tid = threadIdx.x, tx = tid & 15, ty = tid >> 4;
    const int qi = blockIdx.x >> 3, b = blockIdx.x & 7;
    const int q0 = qi * 64;
    const int bid0 = (31 - qi) * 16 + b;
    const int bid1 = bid0 + 8;

    #pragma unroll
    for (int i = tid; i < 64 * 16; i += 256) {
        int r = i >> 4, c4 = (i & 15) * 4;
        *(float4*)&w0s[r][c4] = *(const float4*)&W0[(size_t)r * DOUT + c4];
    }

    #pragma unroll
    for (int rr = 0; rr < 4; rr++) {
        int r = ty + rr * 16;
        float pm0 = g_ml[bid0][0][r], pl0 = g_ml[bid0][1][r];
        float pm1 = g_ml[bid1][0][r], pl1 = g_ml[bid1][1][r];
        float M  = fmaxf(pm0, pm1);
        float f0 = __expf(pm0 - M), f1 = __expf(pm1 - M);
        float inv = 1.f / (pl0 * f0 + pl1 * f1);
        float w0f = f0 * inv, w1f = f1 * inv;
        float4 p0 = *(const float4*)&g_part[bid0][r][tx * 4];
        float4 p1 = *(const float4*)&g_part[bid1][r][tx * 4];
        cs[r][tx * 4 + 0] = p0.x * w0f + p1.x * w1f;
        cs[r][tx * 4 + 1] = p0.y * w0f + p1.y * w1f;
        cs[r][tx * 4 + 2] = p0.z * w0f + p1.z * w1f;
        cs[r][tx * 4 + 3] = p0.w * w0f + p1.w * w1f;
    }
    __syncthreads();

    float o[4][4];
    #pragma unroll
    for (int rr = 0; rr < 4; rr++)
        #pragma unroll
        for (int cc = 0; cc < 4; cc++) o[rr][cc] = 0.f;

    #pragma unroll 8
    for (int k = 0; k < 64; k++) {
        float cr[4], wr[4];
        #pragma unroll
        for (int rr = 0; rr < 4; rr++) cr[rr] = cs[ty + rr * 16][k];
        #pragma unroll
        for (int cc = 0; cc < 4; cc++) wr[cc] = w0s[k][tx + cc * 16];
        #pragma unroll
        for (int rr = 0; rr < 4; rr++)
            #pragma unroll
            for (int cc = 0; cc < 4; cc++)
                o[rr][cc] += cr[rr] * wr[cc];
    }

    #pragma unroll
    for (int rr = 0; rr < 4; rr++)
        #pragma unroll
        for (int cc = 0; cc < 4; cc++)
            out[(size_t)(b * SEQ + q0 + ty + rr * 16) * DOUT + tx + cc * 16] =
                o[rr][cc] + b0[tx + cc * 16];
}

// ---------------------------------------------------------------------------
// Launch
// ---------------------------------------------------------------------------
extern "C" void kernel_launch(void* const* d_in, const int* in_sizes, int n_in,
                              void* d_out, int out_size)
{
    const float* X  = (const float*)d_in[0];
    const float* Wk = (const float*)d_in[1];
    const float* bk = (const float*)d_in[2];
    const float* Wq = (const float*)d_in[3];
    const float* bq = (const float*)d_in[4];
    const float* Wv = (const float*)d_in[5];
    const float* bv = (const float*)d_in[6];
    const float* W0 = (const float*)d_in[7];
    const float* b0 = (const float*)d_in[8];
    float* out = (float*)d_out;

    (void)in_sizes; (void)n_in; (void)out_size;

    proj_kernel<<<512, 128>>>(X, Wk, bk, Wq, bq, Wv, bv);

    cudaFuncSetAttribute(attn_kernel,
                         cudaFuncAttributeMaxDynamicSharedMemorySize,
                         ATTN_SMEM_BYTES);
    attn_kernel<<<512, 128, ATTN_SMEM_BYTES>>>();

    combine_kernel<<<256, 256>>>(out, W0, b0);
}

// round 15
// speedup vs baseline: 1.5724x; 1.5724x over previous
#include <cuda_runtime.h>
#include <cuda_bf16.h>
#include <cstddef>

#define BATCH   8
#define SEQ     2048
#define DMODEL  1024
#define DINT    64
#define DOUT    64
#define BT      (BATCH * SEQ)

// Static device scratch (no allocations), 16B-aligned for vector access.
__device__ __align__(16) float g_qkv[3][(size_t)BT * DINT];   // projected K,Q,V
__device__ __align__(16) float g_part[512][64][64];           // split-K partial ctx
__device__ __align__(16) float g_ml[512][2][64];              // split-K m (0), l (1)

// ---------------------------------------------------------------------------
// tf32 mma.sync m16n8k8 (raw fp32 bits as tf32 operands — HW reads top 19 bits)
// A frag: a0:(g,t) a1:(g+8,t) a2:(g,t+4) a3:(g+8,t+4)   [g=lane>>2, t=lane&3]
// B frag: b0:(k=t,n=g) b1:(k=t+4,n=g)
// C frag: c0:(g,2t) c1:(g,2t+1) c2:(g+8,2t) c3:(g+8,2t+1)
// ---------------------------------------------------------------------------
__device__ __forceinline__ void mma_tf32(float* c, const unsigned* a, const unsigned* b) {
    asm volatile(
        "mma.sync.aligned.m16n8k8.row.col.f32.tf32.tf32.f32 "
        "{%0,%1,%2,%3}, {%4,%5,%6,%7}, {%8,%9}, {%0,%1,%2,%3};\n"
        : "+f"(c[0]), "+f"(c[1]), "+f"(c[2]), "+f"(c[3])
        : "r"(a[0]), "r"(a[1]), "r"(a[2]), "r"(a[3]), "r"(b[0]), "r"(b[1]));
}

// ---------------------------------------------------------------------------
// Kernel 1: fused QKV projection (tf32), register double-buffered LDGs.
// Block: 64 rows x 192 cols (ALL of K|Q|V), 256 threads = 8 warps (2x4),
// warp tile 32x48.  Grid = 256 row-tiles.  X read exactly once (64 MB).
// Pipeline: STS(regs) -> bar -> LDG(next chunk) -> MMA compute -> bar.
// ---------------------------------------------------------------------------
#define PKC 32
#define SXS 36    // xs stride (words): A-load banks g*4+t  -> conflict-free
#define SWS 200   // ws stride (words): B-load banks t*8+g  -> conflict-free
#define NKIT (DMODEL / PKC)   // 32

__global__ void __launch_bounds__(256)
proj_kernel(const float* __restrict__ X,
            const float* __restrict__ Wk, const float* __restrict__ bk,
            const float* __restrict__ Wq, const float* __restrict__ bq,
            const float* __restrict__ Wv, const float* __restrict__ bv)
{
    __shared__ unsigned xs[64 * SXS];
    __shared__ unsigned ws[PKC * SWS];

    const int tid  = threadIdx.x;
    const int wid  = tid >> 5, lane = tid & 31;
    const int g    = lane >> 2, t = lane & 3;
    const int wm   = wid >> 2;                 // 0..1
    const int wn   = wid & 3;                  // 0..3
    const int row0 = blockIdx.x * 64;
    const int wrow = wm * 32;
    const int wcol = wn * 48;

    // ---- fixed per-thread staging coordinates ----
    // X tile [64][32] = 512 uint4, 2 per thread
    const int xr0 = tid >> 3,            xc0 = (tid & 7) * 4;
    const int xr1 = (tid + 256) >> 3,    xc1 = xc0;           // same (i&7)
    const float* xp0 = X + (size_t)(row0 + xr0) * DMODEL + xc0;
    const float* xp1 = X + (size_t)(row0 + xr1) * DMODEL + xc1;
    unsigned* sx0 = &xs[xr0 * SXS + xc0];
    unsigned* sx1 = &xs[xr1 * SXS + xc1];

    // W chunk [32][192] = 1536 uint4, 6 per thread
    const float* wp[6];
    unsigned*    sw[6];
    #pragma unroll
    for (int j = 0; j < 6; j++) {
        int i = tid + j * 256;
        int r = i / 48, f = i - r * 48;
        int col = f * 4;
        const float* wsrc = (col < 64) ? Wk : ((col < 128) ? Wq : Wv);
        wp[j] = wsrc + (size_t)r * 64 + (col & 63);
        sw[j] = &ws[r * SWS + col];
    }

    uint4 xreg[2], wreg[6];

    // prologue: chunk 0 into registers
    xreg[0] = *(const uint4*)xp0;
    xreg[1] = *(const uint4*)xp1;
    #pragma unroll
    for (int j = 0; j < 6; j++) wreg[j] = *(const uint4*)wp[j];

    float acc[2][6][4];
    #pragma unroll
    for (int mi = 0; mi < 2; mi++)
        #pragma unroll
        for (int ni = 0; ni < 6; ni++)
            #pragma unroll
            for (int e = 0; e < 4; e++) acc[mi][ni][e] = 0.f;

    for (int it = 0; it < NKIT; it++) {
        // store current chunk's registers to smem
        *(uint4*)sx0 = xreg[0];
        *(uint4*)sx1 = xreg[1];
        #pragma unroll
        for (int j = 0; j < 6; j++) *(uint4*)sw[j] = wreg[j];
        __syncthreads();

        // kick off next chunk's LDGs (latency hides behind the MMAs below)
        if (it + 1 < NKIT) {
            const size_t xo = (size_t)(it + 1) * PKC;
            const size_t wo = (size_t)(it + 1) * PKC * 64;
            xreg[0] = *(const uint4*)(xp0 + xo);
            xreg[1] = *(const uint4*)(xp1 + xo);
            #pragma unroll
            for (int j = 0; j < 6; j++) wreg[j] = *(const uint4*)(wp[j] + wo);
        }

        // compute on the staged chunk
        #pragma unroll
        for (int ks = 0; ks < PKC; ks += 8) {
            unsigned a[2][4];
            #pragma unroll
            for (int mi = 0; mi < 2; mi++) {
                int r = wrow + mi * 16;
                a[mi][0] = xs[(r + g)     * SXS + ks + t];
                a[mi][1] = xs[(r + g + 8) * SXS + ks + t];
                a[mi][2] = xs[(r + g)     * SXS + ks + t + 4];
                a[mi][3] = xs[(r + g + 8) * SXS + ks + t + 4];
            }
            #pragma unroll
            for (int ni = 0; ni < 6; ni++) {
                unsigned b[2];
                int c0 = wcol + ni * 8;
                b[0] = ws[(ks + t)     * SWS + c0 + g];
                b[1] = ws[(ks + t + 4) * SWS + c0 + g];
                mma_tf32(acc[0][ni], a[0], b);
                mma_tf32(acc[1][ni], a[1], b);
            }
        }
        __syncthreads();
    }

    // epilogue: bias + scatter to g_qkv (p: 0=K, 1=Q, 2=V)
    #pragma unroll
    for (int ni = 0; ni < 6; ni++) {
        int gc = wcol + ni * 8 + 2 * t;            // even, 0..190
        int p  = gc >> 6, cc = gc & 63;
        const float* bs = (p == 0) ? bk : ((p == 1) ? bq : bv);
        float bi0 = bs[cc], bi1 = bs[cc + 1];
        #pragma unroll
        for (int mi = 0; mi < 2; mi++) {
            int r = row0 + wrow + mi * 16 + g;
            *(float2*)&g_qkv[p][(size_t)r * DINT + cc] =
                make_float2(acc[mi][ni][0] + bi0, acc[mi][ni][1] + bi1);
            *(float2*)&g_qkv[p][(size_t)(r + 8) * DINT + cc] =
                make_float2(acc[mi][ni][2] + bi0, acc[mi][ni][3] + bi1);
        }
    }
}

// ---------------------------------------------------------------------------
// Kernel 2: causal flash attention, split-K (2 halves per q-tile).
// BM=64, BN=64, 128 threads = 4 warps x 16 rows, 3 CTAs/SM.
// Grid 512 = 32 q-tiles x 2 halves x 8 batches, largest q-tiles first.
// (Known-good R11 version — attn was not the regression.)
// ---------------------------------------------------------------------------
#define KSS 68
#define VSS 72
#define PSS 68
#define KS_N (64 * KSS)
#define VS_N (64 * VSS)
#define PS_N (64 * PSS)
#define ATTN_SMEM_BYTES ((KS_N + VS_N + PS_N) * (int)sizeof(unsigned))

__global__ void __launch_bounds__(128, 3)
attn_kernel()
{
    extern __shared__ unsigned sm[];
    unsigned* ks = sm;
    unsigned* vs = sm + KS_N;
    unsigned* ps = sm + KS_N + VS_N;   // Q staging, then P

    const int tid = threadIdx.x, wid = tid >> 5, lane = tid & 31;
    const int g = lane >> 2, t = lane & 3;
    const int bid  = blockIdx.x;
    const int qi   = 31 - (bid >> 4);        // largest first
    const int rem  = bid & 15;
    const int half = rem >> 3;
    const int b    = rem & 7;
    const int q0   = qi * 64;
    const int wrow = wid * 16;

    const int n  = qi + 1;
    const int h  = (n + 1) >> 1;
    const int j0 = half ? h : 0;
    const int j1 = half ? n : h;

    const float* Kp = g_qkv[0] + (size_t)b * SEQ * DINT;
    const float* Qp = g_qkv[1] + (size_t)b * SEQ * DINT;
    const float* Vp = g_qkv[2] + (size_t)b * SEQ * DINT;

    // stage Q (pre-scaled by 1/8 — exponent-only, exact) as raw bits
    #pragma unroll
    for (int i = tid; i < 64 * 16; i += 128) {
        int r = i >> 4, c4 = (i & 15) * 4;
        float4 q = *(const float4*)&Qp[(size_t)(q0 + r) * DINT + c4];
        ps[r * PSS + c4 + 0] = __float_as_uint(q.x * 0.125f);
        ps[r * PSS + c4 + 1] = __float_as_uint(q.y * 0.125f);
        ps[r * PSS + c4 + 2] = __float_as_uint(q.z * 0.125f);
        ps[r * PSS + c4 + 3] = __float_as_uint(q.w * 0.125f);
    }
    __syncthreads();

    unsigned qf[8][4];
    #pragma unroll
    for (int kf = 0; kf < 8; kf++) {
        qf[kf][0] = ps[(wrow + g)     * PSS + kf * 8 + t];
        qf[kf][1] = ps[(wrow + g + 8) * PSS + kf * 8 + t];
        qf[kf][2] = ps[(wrow + g)     * PSS + kf * 8 + t + 4];
        qf[kf][3] = ps[(wrow + g + 8) * PSS + kf * 8 + t + 4];
    }
    __syncthreads();

    float ctx[8][4];
    #pragma unroll
    for (int nf = 0; nf < 8; nf++)
        #pragma unroll
        for (int e = 0; e < 4; e++) ctx[nf][e] = 0.f;
    float m0 = -1e30f, m1 = -1e30f, l0 = 0.f, l1 = 0.f;

    for (int j = j0; j < j1; j++) {
        const int k0 = j * 64;

        // stage K/V as raw bits (uint4 copies)
        #pragma unroll
        for (int i = tid; i < 64 * 16; i += 128) {
            int r = i >> 4, c4 = (i & 15) * 4;
            uint4 kv = *(const uint4*)&Kp[(size_t)(k0 + r) * DINT + c4];
            uint4 vv = *(const uint4*)&Vp[(size_t)(k0 + r) * DINT + c4];
            *(uint4*)&ks[r * KSS + c4] = kv;
            *(uint4*)&vs[r * VSS + c4] = vv;
        }
        __syncthreads();

        // ---- S = Q K^T ----
        float s[8][4];
        #pragma unroll
        for (int nf = 0; nf < 8; nf++)
            #pragma unroll
            for (int e = 0; e < 4; e++) s[nf][e] = 0.f;

        #pragma unroll
        for (int kf = 0; kf < 8; kf++) {
            #pragma unroll
            for (int nf = 0; nf < 8; nf++) {
                unsigned bb[2];
                bb[0] = ks[(nf * 8 + g) * KSS + kf * 8 + t];
                bb[1] = ks[(nf * 8 + g) * KSS + kf * 8 + t + 4];
                mma_tf32(s[nf], qf[kf], bb);
            }
        }

        // causal mask (diagonal tile only)
        if (k0 + 63 > q0 + wrow) {
            const int r0r = q0 + wrow + g, r1r = r0r + 8;
            #pragma unroll
            for (int nf = 0; nf < 8; nf++) {
                int key = k0 + nf * 8 + 2 * t;
                if (key     > r0r) s[nf][0] = -1e30f;
                if (key + 1 > r0r) s[nf][1] = -1e30f;
                if (key     > r1r) s[nf][2] = -1e30f;
                if (key + 1 > r1r) s[nf][3] = -1e30f;
            }
        }

        // ---- online softmax ----
        float mx0 = -1e30f, mx1 = -1e30f;
        #pragma unroll
        for (int nf = 0; nf < 8; nf++) {
            mx0 = fmaxf(mx0, fmaxf(s[nf][0], s[nf][1]));
            mx1 = fmaxf(mx1, fmaxf(s[nf][2], s[nf][3]));
        }
        mx0 = fmaxf(mx0, __shfl_xor_sync(0xffffffffu, mx0, 1));
        mx0 = fmaxf(mx0, __shfl_xor_sync(0xffffffffu, mx0, 2));
        mx1 = fmaxf(mx1, __shfl_xor_sync(0xffffffffu, mx1, 1));
        mx1 = fmaxf(mx1, __shfl_xor_sync(0xffffffffu, mx1, 2));

        const float nm0 = fmaxf(m0, mx0), nm1 = fmaxf(m1, mx1);
        const float f0 = __expf(m0 - nm0), f1 = __expf(m1 - nm1);

        float rs0 = 0.f, rs1 = 0.f;
        #pragma unroll
        for (int nf = 0; nf < 8; nf++) {
            float p00 = __expf(s[nf][0] - nm0);
            float p01 = __expf(s[nf][1] - nm0);
            float p10 = __expf(s[nf][2] - nm1);
            float p11 = __expf(s[nf][3] - nm1);
            rs0 += p00 + p01;
            rs1 += p10 + p11;
            ps[(wrow + g)     * PSS + nf * 8 + 2 * t]     = __float_as_uint(p00);
            ps[(wrow + g)     * PSS + nf * 8 + 2 * t + 1] = __float_as_uint(p01);
            ps[(wrow + g + 8) * PSS + nf * 8 + 2 * t]     = __float_as_uint(p10);
            ps[(wrow + g + 8) * PSS + nf * 8 + 2 * t + 1] = __float_as_uint(p11);
        }
        rs0 += __shfl_xor_sync(0xffffffffu, rs0, 1);
        rs0 += __shfl_xor_sync(0xffffffffu, rs0, 2);
        rs1 += __shfl_xor_sync(0xffffffffu, rs1, 1);
        rs1 += __shfl_xor_sync(0xffffffffu, rs1, 2);

        l0 = l0 * f0 + rs0;  m0 = nm0;
        l1 = l1 * f1 + rs1;  m1 = nm1;
        #pragma unroll
        for (int nf = 0; nf < 8; nf++) {
            ctx[nf][0] *= f0; ctx[nf][1] *= f0;
            ctx[nf][2] *= f1; ctx[nf][3] *= f1;
        }
        __syncwarp();   // own-warp P stores -> own-warp A-frag loads

        // ---- ctx += P V ----
        #pragma unroll
        for (int kf = 0; kf < 8; kf++) {
            unsigned pa[4];
            pa[0] = ps[(wrow + g)     * PSS + kf * 8 + t];
            pa[1] = ps[(wrow + g + 8) * PSS + kf * 8 + t];
            pa[2] = ps[(wrow + g)     * PSS + kf * 8 + t + 4];
            pa[3] = ps[(wrow + g + 8) * PSS + kf * 8 + t + 4];
            #pragma unroll
            for (int nf = 0; nf < 8; nf++) {
                unsigned bb[2];
                bb[0] = vs[(kf * 8 + t)     * VSS + nf * 8 + g];
                bb[1] = vs[(kf * 8 + t + 4) * VSS + nf * 8 + g];
                mma_tf32(ctx[nf], pa, bb);
            }
        }
        __syncthreads();
    }

    // ---- write partial state to scratch ----
    if (t == 0) {
        int r = wrow + g;
        g_ml[bid][0][r]     = m0;  g_ml[bid][1][r]     = l0;
        g_ml[bid][0][r + 8] = m1;  g_ml[bid][1][r + 8] = l1;
    }
    #pragma unroll
    for (int nf = 0; nf < 8; nf++) {
        *(float2*)&g_part[bid][wrow + g][nf * 8 + 2 * t] =
            make_float2(ctx[nf][0], ctx[nf][1]);
        *(float2*)&g_part[bid][wrow + g + 8][nf * 8 + 2 * t] =
            make_float2(ctx[nf][2], ctx[nf][3]);
    }
}

// ---------------------------------------------------------------------------
// Kernel 3: merge split-K halves + output projection + bias (fp32 FFMA).
// Grid 256 = 32 q-tiles x 8 batches, 256 threads (16x16, 4x4 tiles).
// ---------------------------------------------------------------------------
#define W0S 68   // stride mult of 4 words: float4 staging stays 16B-aligned

__global__ void __launch_bounds__(256)
combine_kernel(float* __restrict__ out,
               const float* __restrict__ W0, const float* __restrict__ b0)
{
    __shared__ float cs[64][65];       // scalar access only
    __shared__ float w0s[64][W0S];     // float4-staged

    const int tid = threadIdx.x, tx = tid & 15, ty = tid >> 4;
    const int qi = blockIdx.x >> 3, b = blockIdx.x & 7;
    const int q0 = qi * 64;
    const int bid0 = (31 - qi) * 16 + b;
    const int bid1 = bid0 + 8;

    #pragma unroll
    for (int i = tid; i < 64 * 16; i += 256) {
        int r = i >> 4, c4 = (i & 15) * 4;
        *(float4*)&w0s[r][c4] = *(const float4*)&W0[(size_t)r * DOUT + c4];
    }

    #pragma unroll
    for (int rr = 0; rr < 4; rr++) {
        int r = ty + rr * 16;
        float pm0 = g_ml[bid0][0][r], pl0 = g_ml[bid0][1][r];
        float pm1 = g_ml[bid1][0][r], pl1 = g_ml[bid1][1][r];
        float M  = fmaxf(pm0, pm1);
        float f0 = __expf(pm0 - M), f1 = __expf(pm1 - M);
        float inv = 1.f / (pl0 * f0 + pl1 * f1);
        float w0f = f0 * inv, w1f = f1 * inv;
        float4 p0 = *(const float4*)&g_part[bid0][r][tx * 4];
        float4 p1 = *(const float4*)&g_part[bid1][r][tx * 4];
        cs[r][tx * 4 + 0] = p0.x * w0f + p1.x * w1f;
        cs[r][tx * 4 + 1] = p0.y * w0f + p1.y * w1f;
        cs[r][tx * 4 + 2] = p0.z * w0f + p1.z * w1f;
        cs[r][tx * 4 + 3] = p0.w * w0f + p1.w * w1f;
    }
    __syncthreads();

    float o[4][4];
    #pragma unroll
    for (int rr = 0; rr < 4; rr++)
        #pragma unroll
        for (int cc = 0; cc < 4; cc++) o[rr][cc] = 0.f;

    #pragma unroll 8
    for (int k = 0; k < 64; k++) {
        float cr[4], wr[4];
        #pragma unroll
        for (int rr = 0; rr < 4; rr++) cr[rr] = cs[ty + rr * 16][k];
        #pragma unroll
        for (int cc = 0; cc < 4; cc++) wr[cc] = w0s[k][tx + cc * 16];
        #pragma unroll
        for (int rr = 0; rr < 4; rr++)
            #pragma unroll
            for (int cc = 0; cc < 4; cc++)
                o[rr][cc] += cr[rr] * wr[cc];
    }

    #pragma unroll
    for (int rr = 0; rr < 4; rr++)
        #pragma unroll
        for (int cc = 0; cc < 4; cc++)
            out[(size_t)(b * SEQ + q0 + ty + rr * 16) * DOUT + tx + cc * 16] =
                o[rr][cc] + b0[tx + cc * 16];
}

// ---------------------------------------------------------------------------
// Launch
// ---------------------------------------------------------------------------
extern "C" void kernel_launch(void* const* d_in, const int* in_sizes, int n_in,
                              void* d_out, int out_size)
{
    const float* X  = (const float*)d_in[0];
    const float* Wk = (const float*)d_in[1];
    const float* bk = (const float*)d_in[2];
    const float* Wq = (const float*)d_in[3];
    const float* bq = (const float*)d_in[4];
    const float* Wv = (const float*)d_in[5];
    const float* bv = (const float*)d_in[6];
    const float* W0 = (const float*)d_in[7];
    const float* b0 = (const float*)d_in[8];
    float* out = (float*)d_out;

    (void)in_sizes; (void)n_in; (void)out_size;

    proj_kernel<<<256, 256>>>(X, Wk, bk, Wq, bq, Wv, bv);

    cudaFuncSetAttribute(attn_kernel,
                         cudaFuncAttributeMaxDynamicSharedMemorySize,
                         ATTN_SMEM_BYTES);
    attn_kernel<<<512, 128, ATTN_SMEM_BYTES>>>();

    combine_kernel<<<256, 256>>>(out, W0, b0);
}